// round 2
// baseline (speedup 1.0000x reference)
#include <cuda_runtime.h>
#include <cuda_bf16.h>
#include <cstdint>

// ---------------------------------------------------------------------------
// Problem dims
// ---------------------------------------------------------------------------
#define BATCH 128
#define SLEN  1024
#define NSENT 64
#define QLEN  64
#define EMB   50
#define RUN   400     // R
#define MEM   300     // M
#define VOC   2000    // V

// ---------------------------------------------------------------------------
// Device scratch (static globals; no allocation anywhere)
// ---------------------------------------------------------------------------
__device__ float g_table_i[1024 * 3 * RUN];
__device__ float g_table_q[64 * 3 * RUN];
__device__ float g_hinfo[(size_t)BATCH * SLEN * RUN];
__device__ float g_hq[(size_t)BATCH * QLEN * RUN];
__device__ float g_prod[(size_t)BATCH * NSENT * RUN];
__device__ float g_xzm[(size_t)BATCH * NSENT * 3 * MEM];
__device__ float g_hidden[(size_t)BATCH * NSENT * MEM];
__device__ float g_xza[(size_t)BATCH * NSENT * 3 * VOC];
__device__ float g_rec[(size_t)BATCH * 3 * VOC];
__device__ float g_hA[(size_t)BATCH * VOC];
__device__ float g_hB[(size_t)BATCH * VOC];

// software grid barrier state
__device__ unsigned g_count = 0;
__device__ volatile unsigned g_sense = 0;

__device__ __forceinline__ float sigmoidf_(float x) { return 1.f / (1.f + expf(-x)); }

__device__ __forceinline__ void grid_barrier(unsigned G, unsigned& sense) {
    __syncthreads();
    sense ^= 1u;
    if (threadIdx.x == 0 && threadIdx.y == 0) {
        __threadfence();
        unsigned prev = atomicAdd(&g_count, 1u);
        if (prev == G - 1u) {
            g_count = 0u;
            __threadfence();
            g_sense = sense;
        } else {
            while (g_sense != sense) { __nanosleep(64); }
        }
        __threadfence();
    }
    __syncthreads();
}

// ---------------------------------------------------------------------------
// table[v, j] = sum_e emb[v,e] * W[e,j] + b0[j]
// ---------------------------------------------------------------------------
__global__ void build_table_kernel(const float* __restrict__ emb,
                                   const float* __restrict__ W,
                                   const float* __restrict__ b0,
                                   float* __restrict__ table,
                                   int N3) {
    int v = blockIdx.y;
    int j = blockIdx.x * blockDim.x + threadIdx.x;
    __shared__ float se[EMB];
    if (threadIdx.x < EMB) se[threadIdx.x] = emb[(size_t)v * EMB + threadIdx.x];
    __syncthreads();
    if (j < N3) {
        float acc = b0[j];
#pragma unroll 10
        for (int e = 0; e < EMB; ++e) acc += se[e] * W[(size_t)e * N3 + j];
        table[(size_t)v * N3 + j] = acc;
    }
}

// ---------------------------------------------------------------------------
// Persistent fused GRU over all T timesteps. One launch per GRU.
//   grid = (ceil(H/32), 8), block = (32,8). 1 CTA/SM (big smem) -> co-resident.
//   U column-slice kept in SMEM for the whole kernel.
//   xz row: tok != null -> table[tok[b*T+t]] ; else xz[(b*T+t)*3H].
//   seq_out: stores h (optionally * pad(t <= num_sent[b])).
// ---------------------------------------------------------------------------
__global__ void __launch_bounds__(256, 1)
gru_seq_kernel(const float* __restrict__ xz,
               const int* __restrict__ tok,
               const float* __restrict__ U,
               const float* __restrict__ brec,
               float* __restrict__ hP, float* __restrict__ hQ,
               float* __restrict__ seq_out,
               const int* __restrict__ num_sent,
               int T, int H) {
    extern __shared__ float smem[];
    float* su  = smem;             // [H][96]   U slice, cols j0..j0+31 x 3 gates
    float* shh = smem + H * 96;    // [16][H]   staged h_prev rows

    const int tx = threadIdx.x, ty = threadIdx.y;
    const int tid = ty * 32 + tx;
    const int j0 = blockIdx.x * 32;
    const int b0 = blockIdx.y * 16;
    const int N3 = 3 * H;
    const unsigned G = gridDim.x * gridDim.y;
    unsigned sense = g_sense;

    // load U slice once
    for (int e = tid; e < H * 96; e += 256) {
        int k = e / 96, c = e % 96;
        int g = c >> 5, j = j0 + (c & 31);
        su[e] = (j < H) ? U[(size_t)k * N3 + g * H + j] : 0.f;
    }
    // zero initial hidden state (this CTA's region of hP)
    for (int e = tid; e < 16 * 32; e += 256) {
        int bb = e >> 5, jj = e & 31;
        if (j0 + jj < H) hP[(size_t)(b0 + bb) * H + j0 + jj] = 0.f;
    }
    grid_barrier(G, sense);

    float* hp = hP;
    float* hn = hQ;
    const int j = j0 + tx;
    float bz = 0.f, br = 0.f, bh = 0.f;
    if (j < H) { bz = brec[j]; br = brec[H + j]; bh = brec[2 * H + j]; }

    for (int t = 0; t < T; ++t) {
        // stage h_prev rows b0..b0+15 into smem (coalesced)
        for (int e = tid; e < 16 * H; e += 256) {
            int row = e / H, k = e - row * H;
            shh[row * H + k] = hp[(size_t)(b0 + row) * H + k];
        }
        __syncthreads();

        float accz0 = 0.f, accz1 = 0.f, accr0 = 0.f, accr1 = 0.f, acch0 = 0.f, acch1 = 0.f;
        const float* s0 = shh + ty * H;
        const float* s1 = shh + (ty + 8) * H;
#pragma unroll 4
        for (int k = 0; k < H; ++k) {
            float uz = su[k * 96 + tx];
            float ur = su[k * 96 + 32 + tx];
            float uh = su[k * 96 + 64 + tx];
            float h0 = s0[k], h1 = s1[k];
            accz0 += h0 * uz; accz1 += h1 * uz;
            accr0 += h0 * ur; accr1 += h1 * ur;
            acch0 += h0 * uh; acch1 += h1 * uh;
        }

        if (j < H) {
#pragma unroll
            for (int r = 0; r < 2; ++r) {
                const int b = b0 + ty + 8 * r;
                const float* xrow;
                if (tok) xrow = xz + (size_t)tok[(size_t)b * T + t] * N3;
                else     xrow = xz + ((size_t)b * T + t) * N3;
                float az = (r == 0) ? accz0 : accz1;
                float ar = (r == 0) ? accr0 : accr1;
                float ah = (r == 0) ? acch0 : acch1;
                float z  = sigmoidf_(xrow[j] + az + bz);
                float rr = sigmoidf_(xrow[H + j] + ar + br);
                float hh = tanhf(xrow[2 * H + j] + rr * (ah + bh));
                float hprev = shh[(ty + 8 * r) * H + j0 + tx];  // careful: need h_prev[b][j]
                // shh holds row (ty+8r) full H values; index j
                hprev = shh[(ty + 8 * r) * H + j];
                float hnew = z * hprev + (1.f - z) * hh;
                hn[(size_t)b * H + j] = hnew;
                float padv = 1.f;
                if (num_sent) padv = (t <= num_sent[b]) ? 1.f : 0.f;
                seq_out[((size_t)b * T + t) * H + j] = hnew * padv;
            }
        }
        grid_barrier(G, sense);
        float* tmp = hp; hp = hn; hn = tmp;
    }
}

// ---------------------------------------------------------------------------
// prod[b,n,:] = h_info[b, info_idx[b,n], :] * h_q[b, qidx[b]-1, :] * pad(b,n)
// ---------------------------------------------------------------------------
__global__ void prod_kernel(const float* __restrict__ hinfo,
                            const float* __restrict__ hq,
                            const int* __restrict__ info_idx,
                            const int* __restrict__ num_sent,
                            const int* __restrict__ qidx,
                            float* __restrict__ prod) {
    const int nn = blockIdx.x;
    const int b  = blockIdx.y;
    const int si = info_idx[b * NSENT + nn];
    const int qi = qidx[b] - 1;
    const float padv = (nn <= num_sent[b]) ? 1.f : 0.f;
    const float* hi  = hinfo + ((size_t)b * SLEN + si) * RUN;
    const float* hqr = hq + ((size_t)b * QLEN + qi) * RUN;
    float* pr = prod + ((size_t)b * NSENT + nn) * RUN;
    for (int jj = threadIdx.x; jj < RUN; jj += blockDim.x)
        pr[jj] = hi[jj] * hqr[jj] * padv;
}

// ---------------------------------------------------------------------------
// Generic C[M,N] = A[M,K] @ W[K,N] + bias[N].  64x64 tile, BK=16, 4x4/thread.
// ---------------------------------------------------------------------------
__global__ void gemm_bias_kernel(const float* __restrict__ A,
                                 const float* __restrict__ W,
                                 const float* __restrict__ bias,
                                 float* __restrict__ C,
                                 int Mdim, int Kdim, int Ndim) {
    __shared__ __align__(16) float As[16][68];
    __shared__ __align__(16) float Bs[16][68];
    const int tid = threadIdx.x;
    const int tx = tid & 15;
    const int ty = tid >> 4;
    const int m0 = blockIdx.y * 64;
    const int n0 = blockIdx.x * 64;

    float acc[4][4];
#pragma unroll
    for (int i = 0; i < 4; ++i)
#pragma unroll
        for (int jj = 0; jj < 4; ++jj) acc[i][jj] = 0.f;

    for (int k0 = 0; k0 < Kdim; k0 += 16) {
        for (int e = tid; e < 1024; e += 256) {
            int mm = e >> 4, kk = e & 15;
            int m = m0 + mm, k = k0 + kk;
            As[kk][mm] = (m < Mdim && k < Kdim) ? A[(size_t)m * Kdim + k] : 0.f;
        }
        for (int e = tid; e < 1024; e += 256) {
            int kk = e >> 6, nn = e & 63;
            int k = k0 + kk, nv = n0 + nn;
            Bs[kk][nn] = (k < Kdim && nv < Ndim) ? W[(size_t)k * Ndim + nv] : 0.f;
        }
        __syncthreads();
#pragma unroll
        for (int kk = 0; kk < 16; ++kk) {
            float4 a4 = *reinterpret_cast<const float4*>(&As[kk][ty * 4]);
            float4 b4 = *reinterpret_cast<const float4*>(&Bs[kk][tx * 4]);
            float av[4] = {a4.x, a4.y, a4.z, a4.w};
            float bv[4] = {b4.x, b4.y, b4.z, b4.w};
#pragma unroll
            for (int i = 0; i < 4; ++i)
#pragma unroll
                for (int jj = 0; jj < 4; ++jj) acc[i][jj] += av[i] * bv[jj];
        }
        __syncthreads();
    }
#pragma unroll
    for (int i = 0; i < 4; ++i) {
        int m = m0 + ty * 4 + i;
        if (m >= Mdim) continue;
#pragma unroll
        for (int jj = 0; jj < 4; ++jj) {
            int nv = n0 + tx * 4 + jj;
            if (nv < Ndim) C[(size_t)m * Ndim + nv] = acc[i][jj] + bias[nv];
        }
    }
}

// ---------------------------------------------------------------------------
// Persistent answer GRU: 64 steps of
//   phase A: rec[128,6000] = h @ Ua + ba1   (32x64 tiles, K=2000)
//   phase B: gates + softmax + combine (one CTA per batch row)
// grid = 148 CTAs x 256 threads.
// ---------------------------------------------------------------------------
#define ANS_G 148
#define NTM 4                       // 128/32
#define NTN ((3 * VOC + 63) / 64)   // 94
__global__ void __launch_bounds__(256, 1)
answer_kernel(const float* __restrict__ xza,
              const float* __restrict__ Ua,
              const float* __restrict__ ba1,
              float* __restrict__ rec,
              float* __restrict__ hP, float* __restrict__ hQ,
              float* __restrict__ out) {
    __shared__ __align__(16) float As[16][36];
    __shared__ __align__(16) float Bs[16][68];
    __shared__ float red[256];

    const int tid = threadIdx.x;
    const unsigned G = gridDim.x;
    unsigned sense = g_sense;

    // zero initial hidden state
    for (int e = blockIdx.x * 256 + tid; e < BATCH * VOC; e += G * 256)
        hP[e] = 0.f;
    grid_barrier(G, sense);

    float* hp = hP;
    float* hn = hQ;
    const int txn = tid & 15;   // n-group (4 cols)
    const int tym = tid >> 4;   // m-group (2 rows)

    for (int n = 0; n < NSENT; ++n) {
        // ----- phase A: rec = hp @ Ua + ba1 -----
        for (int tile = blockIdx.x; tile < NTM * NTN; tile += G) {
            const int tm = tile % NTM;
            const int tn = tile / NTM;
            const int m0 = tm * 32;
            const int n0 = tn * 64;
            float acc[2][4];
#pragma unroll
            for (int i = 0; i < 2; ++i)
#pragma unroll
                for (int c = 0; c < 4; ++c) acc[i][c] = 0.f;

            for (int k0 = 0; k0 < VOC; k0 += 16) {
                for (int e = tid; e < 512; e += 256) {
                    int mm = e >> 4, kk = e & 15;
                    As[kk][mm] = hp[(size_t)(m0 + mm) * VOC + k0 + kk];
                }
                for (int e = tid; e < 1024; e += 256) {
                    int kk = e >> 6, nn = e & 63;
                    int nc = n0 + nn;
                    Bs[kk][nn] = (nc < 3 * VOC) ? Ua[(size_t)(k0 + kk) * (3 * VOC) + nc] : 0.f;
                }
                __syncthreads();
#pragma unroll
                for (int kk = 0; kk < 16; ++kk) {
                    float a0 = As[kk][tym * 2];
                    float a1 = As[kk][tym * 2 + 1];
                    float4 b4 = *reinterpret_cast<const float4*>(&Bs[kk][txn * 4]);
                    acc[0][0] += a0 * b4.x; acc[0][1] += a0 * b4.y;
                    acc[0][2] += a0 * b4.z; acc[0][3] += a0 * b4.w;
                    acc[1][0] += a1 * b4.x; acc[1][1] += a1 * b4.y;
                    acc[1][2] += a1 * b4.z; acc[1][3] += a1 * b4.w;
                }
                __syncthreads();
            }
#pragma unroll
            for (int i = 0; i < 2; ++i) {
                int m = m0 + tym * 2 + i;
#pragma unroll
                for (int c = 0; c < 4; ++c) {
                    int nc = n0 + txn * 4 + c;
                    if (nc < 3 * VOC)
                        rec[(size_t)m * (3 * VOC) + nc] = acc[i][c] + ba1[nc];
                }
            }
        }
        grid_barrier(G, sense);

        // ----- phase B: gates + softmax + combine -----
        if (blockIdx.x < BATCH) {
            const int b = blockIdx.x;
            const float* xrow = xza + ((size_t)b * NSENT + n) * (3 * VOC);
            const float* rrow = rec + (size_t)b * (3 * VOC);
            float zv[8], tv[8];
            float m = -1e30f;
#pragma unroll
            for (int i = 0; i < 8; ++i) {
                int jj = tid + i * 256;
                if (jj < VOC) {
                    float z = sigmoidf_(xrow[jj] + rrow[jj]);
                    float r = sigmoidf_(xrow[VOC + jj] + rrow[VOC + jj]);
                    float t = xrow[2 * VOC + jj] + r * rrow[2 * VOC + jj];
                    zv[i] = z; tv[i] = t;
                    m = fmaxf(m, t);
                } else { zv[i] = 0.f; tv[i] = -1e30f; }
            }
            red[tid] = m; __syncthreads();
            for (int s = 128; s > 0; s >>= 1) {
                if (tid < s) red[tid] = fmaxf(red[tid], red[tid + s]);
                __syncthreads();
            }
            m = red[0]; __syncthreads();

            float ev[8];
            float sum = 0.f;
#pragma unroll
            for (int i = 0; i < 8; ++i) {
                int jj = tid + i * 256;
                if (jj < VOC) { ev[i] = expf(tv[i] - m); sum += ev[i]; }
                else ev[i] = 0.f;
            }
            red[tid] = sum; __syncthreads();
            for (int s = 128; s > 0; s >>= 1) {
                if (tid < s) red[tid] += red[tid + s];
                __syncthreads();
            }
            const float inv = 1.f / red[0];
            __syncthreads();

#pragma unroll
            for (int i = 0; i < 8; ++i) {
                int jj = tid + i * 256;
                if (jj < VOC) {
                    float hh = ev[i] * inv;
                    float z  = zv[i];
                    float hprev = hp[(size_t)b * VOC + jj];
                    float hnew = z * hprev + (1.f - z) * hh;
                    hn[(size_t)b * VOC + jj] = hnew;
                    out[((size_t)b * NSENT + n) * VOC + jj] = hnew;
                }
            }
        }
        grid_barrier(G, sense);
        float* tmp = hp; hp = hn; hn = tmp;
    }
}

// ---------------------------------------------------------------------------
// Host orchestration: ~9 graph nodes total.
// ---------------------------------------------------------------------------
extern "C" void kernel_launch(void* const* d_in, const int* in_sizes, int n_in,
                              void* d_out, int out_size) {
    const int*   info      = (const int*)d_in[0];
    const int*   info_idx  = (const int*)d_in[1];
    const int*   num_sent  = (const int*)d_in[2];
    const int*   question  = (const int*)d_in[3];
    const int*   qidx      = (const int*)d_in[4];
    const float* info_emb  = (const float*)d_in[5];
    const float* Wi        = (const float*)d_in[6];
    const float* Ui        = (const float*)d_in[7];
    const float* bi        = (const float*)d_in[8];
    const float* q_emb     = (const float*)d_in[9];
    const float* Wq        = (const float*)d_in[10];
    const float* Uq        = (const float*)d_in[11];
    const float* bq        = (const float*)d_in[12];
    const float* Wm        = (const float*)d_in[13];
    const float* Um        = (const float*)d_in[14];
    const float* bm        = (const float*)d_in[15];
    const float* Wa        = (const float*)d_in[16];
    const float* Ua        = (const float*)d_in[17];
    const float* ba        = (const float*)d_in[18];
    float* out = (float*)d_out;

    float *tbl_i, *tbl_q, *hinfo, *hq, *prod, *xzm, *hidden, *xza, *rec, *hA, *hB;
    cudaGetSymbolAddress((void**)&tbl_i, g_table_i);
    cudaGetSymbolAddress((void**)&tbl_q, g_table_q);
    cudaGetSymbolAddress((void**)&hinfo, g_hinfo);
    cudaGetSymbolAddress((void**)&hq, g_hq);
    cudaGetSymbolAddress((void**)&prod, g_prod);
    cudaGetSymbolAddress((void**)&xzm, g_xzm);
    cudaGetSymbolAddress((void**)&hidden, g_hidden);
    cudaGetSymbolAddress((void**)&xza, g_xza);
    cudaGetSymbolAddress((void**)&rec, g_rec);
    cudaGetSymbolAddress((void**)&hA, g_hA);
    cudaGetSymbolAddress((void**)&hB, g_hB);

    // allow big dynamic smem for the persistent GRU kernel
    static bool attr_set = false;
    if (!attr_set) {
        cudaFuncSetAttribute(gru_seq_kernel,
                             cudaFuncAttributeMaxDynamicSharedMemorySize, 200 * 1024);
        attr_set = true;
    }

    // --- token tables: emb @ W + b[0]
    build_table_kernel<<<dim3((3 * RUN + 255) / 256, 1024), 256>>>(info_emb, Wi, bi, tbl_i, 3 * RUN);
    build_table_kernel<<<dim3((3 * RUN + 255) / 256, 64), 256>>>(q_emb, Wq, bq, tbl_q, 3 * RUN);

    const dim3 blk(32, 8);

    // --- info GRU (T=1024, H=400): 13x8 = 104 CTAs, 1 launch
    {
        size_t smem = (size_t)RUN * 96 * 4 + (size_t)16 * RUN * 4;   // 179200 B
        gru_seq_kernel<<<dim3((RUN + 31) / 32, 8), blk, smem>>>(
            tbl_i, info, Ui, bi + 3 * RUN, hA, hB, hinfo, nullptr, SLEN, RUN);
    }
    // --- question GRU (T=64, H=400)
    {
        size_t smem = (size_t)RUN * 96 * 4 + (size_t)16 * RUN * 4;
        gru_seq_kernel<<<dim3((RUN + 31) / 32, 8), blk, smem>>>(
            tbl_q, question, Uq, bq + 3 * RUN, hA, hB, hq, nullptr, QLEN, RUN);
    }

    // --- prod = gather(h_info) * enc_q * pad
    prod_kernel<<<dim3(NSENT, BATCH), 128>>>(hinfo, hq, info_idx, num_sent, qidx, prod);

    // --- xz_m = prod @ Wm + bm[0]   [8192,400]x[400,900]
    gemm_bias_kernel<<<dim3((3 * MEM + 63) / 64, (BATCH * NSENT) / 64), 256>>>(
        prod, Wm, bm, xzm, BATCH * NSENT, RUN, 3 * MEM);

    // --- memory GRU (T=64, H=300): 10x8 = 80 CTAs; seq stores h*pad
    {
        size_t smem = (size_t)MEM * 96 * 4 + (size_t)16 * MEM * 4;   // 134400 B
        gru_seq_kernel<<<dim3((MEM + 31) / 32, 8), blk, smem>>>(
            xzm, nullptr, Um, bm + 3 * MEM, hA, hB, hidden, num_sent, NSENT, MEM);
    }

    // --- xz_a = hidden @ Wa + ba[0]   [8192,300]x[300,6000]
    gemm_bias_kernel<<<dim3((3 * VOC + 63) / 64, (BATCH * NSENT) / 64), 256>>>(
        hidden, Wa, ba, xza, BATCH * NSENT, MEM, 3 * VOC);

    // --- answer GRU (64 steps, fused GEMM + gates + softmax), 1 launch
    answer_kernel<<<ANS_G, 256>>>(xza, Ua, ba + 3 * VOC, rec, hA, hB, out);
}

// round 3
// speedup vs baseline: 2.7306x; 2.7306x over previous
#include <cuda_runtime.h>
#include <cuda_bf16.h>
#include <cstdint>

#define BATCH 128
#define SLEN  1024
#define NSENT 64
#define QLEN  64
#define EMB   50
#define RUN   400
#define MEM   300
#define VOC   2000

// ---------------------------------------------------------------------------
// Device scratch
// ---------------------------------------------------------------------------
__device__ float g_table_i[1024 * 3 * RUN];
__device__ float g_table_q[64 * 3 * RUN];
__device__ float g_hinfo[(size_t)BATCH * SLEN * RUN];
__device__ float g_hq[(size_t)BATCH * QLEN * RUN];
__device__ float g_prod[(size_t)BATCH * NSENT * RUN];
__device__ float g_xzm[(size_t)BATCH * NSENT * 3 * MEM];
__device__ float g_hidden[(size_t)BATCH * NSENT * MEM];
__device__ float g_xza[(size_t)BATCH * NSENT * 3 * VOC];
__device__ float g_rec[(size_t)BATCH * 3 * VOC];
__device__ float g_hA[(size_t)BATCH * VOC];
__device__ float g_hB[(size_t)BATCH * VOC];

__device__ unsigned g_count = 0;
__device__ volatile unsigned g_sense = 0;

__device__ __forceinline__ float sigmoidf_(float x) { return 1.f / (1.f + expf(-x)); }

__device__ __forceinline__ void grid_barrier(unsigned G, unsigned& sense) {
    __syncthreads();
    sense ^= 1u;
    if (threadIdx.x == 0 && threadIdx.y == 0) {
        __threadfence();
        unsigned prev = atomicAdd(&g_count, 1u);
        if (prev == G - 1u) {
            g_count = 0u;
            __threadfence();
            g_sense = sense;
        } else {
            while (g_sense != sense) { __nanosleep(64); }
        }
        __threadfence();
    }
    __syncthreads();
}

// ---------------------------------------------------------------------------
// table[v, j] = sum_e emb[v,e] * W[e,j] + b0[j]
// ---------------------------------------------------------------------------
__global__ void build_table_kernel(const float* __restrict__ emb,
                                   const float* __restrict__ W,
                                   const float* __restrict__ b0,
                                   float* __restrict__ table,
                                   int N3) {
    int v = blockIdx.y;
    int j = blockIdx.x * blockDim.x + threadIdx.x;
    __shared__ float se[EMB];
    if (threadIdx.x < EMB) se[threadIdx.x] = emb[(size_t)v * EMB + threadIdx.x];
    __syncthreads();
    if (j < N3) {
        float acc = b0[j];
#pragma unroll 10
        for (int e = 0; e < EMB; ++e) acc += se[e] * W[(size_t)e * N3 + j];
        table[(size_t)v * N3 + j] = acc;
    }
}

// ---------------------------------------------------------------------------
// Persistent GRU. block (32,4)=128 thr; tile 16 batch x 32 cols; 4 rows/thread.
// grid (ceil(H/32), 8). U col-slice cached in smem whole kernel.
// ---------------------------------------------------------------------------
__global__ void __launch_bounds__(128, 1)
gru_seq_kernel(const float* __restrict__ xz,
               const int* __restrict__ tok,
               const float* __restrict__ U,
               const float* __restrict__ brec,
               float* __restrict__ hP, float* __restrict__ hQ,
               float* __restrict__ seq_out,
               const int* __restrict__ num_sent,
               int T, int H) {
    extern __shared__ float smem[];
    float* su  = smem;             // [H][96]
    float* shh = smem + H * 96;    // [16][H]

    const int tx = threadIdx.x, ty = threadIdx.y;
    const int tid = ty * 32 + tx;
    const int j0 = blockIdx.x * 32;
    const int b0 = blockIdx.y * 16;
    const int N3 = 3 * H;
    const unsigned G = gridDim.x * gridDim.y;
    unsigned sense = g_sense;

    for (int e = tid; e < H * 96; e += 128) {
        int k = e / 96, c = e % 96;
        int g = c >> 5, j = j0 + (c & 31);
        su[e] = (j < H) ? U[(size_t)k * N3 + g * H + j] : 0.f;
    }
    for (int e = tid; e < 16 * 32; e += 128) {
        int bb = e >> 5, jj = e & 31;
        if (j0 + jj < H) hP[(size_t)(b0 + bb) * H + j0 + jj] = 0.f;
    }
    grid_barrier(G, sense);

    float* hp = hP;
    float* hn = hQ;
    const int j = j0 + tx;
    float bz = 0.f, br = 0.f, bh = 0.f;
    if (j < H) { bz = brec[j]; br = brec[H + j]; bh = brec[2 * H + j]; }

    const float* sup = su + tx;

    for (int t = 0; t < T; ++t) {
        for (int e = tid; e < 16 * H; e += 128) {
            int row = e / H, k = e - row * H;
            shh[row * H + k] = hp[(size_t)(b0 + row) * H + k];
        }
        __syncthreads();

        float az[4] = {0,0,0,0}, ar[4] = {0,0,0,0}, ah[4] = {0,0,0,0};
        const float* hr0 = shh + (ty * 4 + 0) * H;
        const float* hr1 = shh + (ty * 4 + 1) * H;
        const float* hr2 = shh + (ty * 4 + 2) * H;
        const float* hr3 = shh + (ty * 4 + 3) * H;
#pragma unroll 8
        for (int k = 0; k < H; ++k) {
            float uz = sup[k * 96];
            float ur = sup[k * 96 + 32];
            float uh = sup[k * 96 + 64];
            float h0 = hr0[k], h1 = hr1[k], h2 = hr2[k], h3 = hr3[k];
            az[0] += h0 * uz; az[1] += h1 * uz; az[2] += h2 * uz; az[3] += h3 * uz;
            ar[0] += h0 * ur; ar[1] += h1 * ur; ar[2] += h2 * ur; ar[3] += h3 * ur;
            ah[0] += h0 * uh; ah[1] += h1 * uh; ah[2] += h2 * uh; ah[3] += h3 * uh;
        }

        if (j < H) {
#pragma unroll
            for (int i = 0; i < 4; ++i) {
                const int row = ty * 4 + i;
                const int b = b0 + row;
                const float* xrow;
                if (tok) xrow = xz + (size_t)tok[(size_t)b * T + t] * N3;
                else     xrow = xz + ((size_t)b * T + t) * N3;
                float z  = sigmoidf_(xrow[j] + az[i] + bz);
                float rr = sigmoidf_(xrow[H + j] + ar[i] + br);
                float hh = tanhf(xrow[2 * H + j] + rr * (ah[i] + bh));
                float hprev = shh[row * H + j];
                float hnew = z * hprev + (1.f - z) * hh;
                hn[(size_t)b * H + j] = hnew;
                float padv = 1.f;
                if (num_sent) padv = (t <= num_sent[b]) ? 1.f : 0.f;
                seq_out[((size_t)b * T + t) * H + j] = hnew * padv;
            }
        }
        grid_barrier(G, sense);
        float* tmp = hp; hp = hn; hn = tmp;
    }
}

// ---------------------------------------------------------------------------
// prod
// ---------------------------------------------------------------------------
__global__ void prod_kernel(const float* __restrict__ hinfo,
                            const float* __restrict__ hq,
                            const int* __restrict__ info_idx,
                            const int* __restrict__ num_sent,
                            const int* __restrict__ qidx,
                            float* __restrict__ prod) {
    const int nn = blockIdx.x;
    const int b  = blockIdx.y;
    const int si = info_idx[b * NSENT + nn];
    const int qi = qidx[b] - 1;
    const float padv = (nn <= num_sent[b]) ? 1.f : 0.f;
    const float* hi  = hinfo + ((size_t)b * SLEN + si) * RUN;
    const float* hqr = hq + ((size_t)b * QLEN + qi) * RUN;
    float* pr = prod + ((size_t)b * NSENT + nn) * RUN;
    for (int jj = threadIdx.x; jj < RUN; jj += blockDim.x)
        pr[jj] = hi[jj] * hqr[jj] * padv;
}

// ---------------------------------------------------------------------------
// Generic C = A@W + bias, 64x64 tile, BK=16, 4x4/thread.
// ---------------------------------------------------------------------------
__global__ void gemm_bias_kernel(const float* __restrict__ A,
                                 const float* __restrict__ W,
                                 const float* __restrict__ bias,
                                 float* __restrict__ C,
                                 int Mdim, int Kdim, int Ndim) {
    __shared__ __align__(16) float As[16][68];
    __shared__ __align__(16) float Bs[16][68];
    const int tid = threadIdx.x;
    const int tx = tid & 15;
    const int ty = tid >> 4;
    const int m0 = blockIdx.y * 64;
    const int n0 = blockIdx.x * 64;

    float acc[4][4];
#pragma unroll
    for (int i = 0; i < 4; ++i)
#pragma unroll
        for (int jj = 0; jj < 4; ++jj) acc[i][jj] = 0.f;

    for (int k0 = 0; k0 < Kdim; k0 += 16) {
        for (int e = tid; e < 1024; e += 256) {
            int mm = e >> 4, kk = e & 15;
            int m = m0 + mm, k = k0 + kk;
            As[kk][mm] = (m < Mdim && k < Kdim) ? A[(size_t)m * Kdim + k] : 0.f;
        }
        for (int e = tid; e < 1024; e += 256) {
            int kk = e >> 6, nn = e & 63;
            int k = k0 + kk, nv = n0 + nn;
            Bs[kk][nn] = (k < Kdim && nv < Ndim) ? W[(size_t)k * Ndim + nv] : 0.f;
        }
        __syncthreads();
#pragma unroll
        for (int kk = 0; kk < 16; ++kk) {
            float4 a4 = *reinterpret_cast<const float4*>(&As[kk][ty * 4]);
            float4 b4 = *reinterpret_cast<const float4*>(&Bs[kk][tx * 4]);
            float av[4] = {a4.x, a4.y, a4.z, a4.w};
            float bv[4] = {b4.x, b4.y, b4.z, b4.w};
#pragma unroll
            for (int i = 0; i < 4; ++i)
#pragma unroll
                for (int jj = 0; jj < 4; ++jj) acc[i][jj] += av[i] * bv[jj];
        }
        __syncthreads();
    }
#pragma unroll
    for (int i = 0; i < 4; ++i) {
        int m = m0 + ty * 4 + i;
        if (m >= Mdim) continue;
#pragma unroll
        for (int jj = 0; jj < 4; ++jj) {
            int nv = n0 + tx * 4 + jj;
            if (nv < Ndim) C[(size_t)m * Ndim + nv] = acc[i][jj] + bias[nv];
        }
    }
}

// ---------------------------------------------------------------------------
// Persistent answer GRU, grid 296 = 2 CTAs/SM, double-buffered K chunks.
// ---------------------------------------------------------------------------
#define ANS_G 296
#define NTM 4
#define NTN ((3 * VOC + 63) / 64)   // 94
#define NCH (VOC / 16)              // 125

__global__ void __launch_bounds__(256, 2)
answer_kernel(const float* __restrict__ xza,
              const float* __restrict__ Ua,
              const float* __restrict__ ba1,
              float* __restrict__ rec,
              float* __restrict__ hP, float* __restrict__ hQ,
              float* __restrict__ out) {
    __shared__ __align__(16) float As[2][16][36];
    __shared__ __align__(16) float Bs[2][16][68];
    __shared__ float red[256];

    const int tid = threadIdx.x;
    const unsigned G = gridDim.x;
    unsigned sense = g_sense;

    for (int e = blockIdx.x * 256 + tid; e < BATCH * VOC; e += G * 256)
        hP[e] = 0.f;
    grid_barrier(G, sense);

    float* hp = hP;
    float* hn = hQ;
    const int txn = tid & 15;
    const int tym = tid >> 4;

    // load element coords (computed once)
    const int amm = tid >> 4;            // for As loads: e in [0,512), 2 passes
    const int akk = tid & 15;
    const int bkk0 = tid >> 6;           // for Bs loads: e in [0,1024), 4 passes
    const int bnn  = tid & 63;

    for (int n = 0; n < NSENT; ++n) {
        // ----- phase A: rec = hp @ Ua + ba1 (double-buffered) -----
        for (int tile = blockIdx.x; tile < NTM * NTN; tile += G) {
            const int tm = tile % NTM;
            const int tn = tile / NTM;
            const int m0 = tm * 32;
            const int n0 = tn * 64;
            float acc[2][4];
#pragma unroll
            for (int i = 0; i < 2; ++i)
#pragma unroll
                for (int c = 0; c < 4; ++c) acc[i][c] = 0.f;

            // preload chunk 0 into buffer 0
            {
                const int k0 = 0;
#pragma unroll
                for (int p = 0; p < 2; ++p) {
                    int mm = amm + p * 16;
                    As[0][akk][mm] = hp[(size_t)(m0 + mm) * VOC + k0 + akk];
                }
#pragma unroll
                for (int p = 0; p < 4; ++p) {
                    int kk = bkk0 + p * 4;
                    int nc = n0 + bnn;
                    Bs[0][kk][bnn] = (nc < 3 * VOC) ? Ua[(size_t)(k0 + kk) * (3 * VOC) + nc] : 0.f;
                }
            }

            int cur = 0;
            for (int ch = 0; ch < NCH; ++ch) {
                __syncthreads();
                // prefetch next chunk into other buffer
                if (ch + 1 < NCH) {
                    const int k0 = (ch + 1) * 16;
                    const int nxt = cur ^ 1;
#pragma unroll
                    for (int p = 0; p < 2; ++p) {
                        int mm = amm + p * 16;
                        As[nxt][akk][mm] = hp[(size_t)(m0 + mm) * VOC + k0 + akk];
                    }
#pragma unroll
                    for (int p = 0; p < 4; ++p) {
                        int kk = bkk0 + p * 4;
                        int nc = n0 + bnn;
                        Bs[nxt][kk][bnn] = (nc < 3 * VOC) ? Ua[(size_t)(k0 + kk) * (3 * VOC) + nc] : 0.f;
                    }
                }
                // compute current chunk
#pragma unroll
                for (int kk = 0; kk < 16; ++kk) {
                    float a0 = As[cur][kk][tym * 2];
                    float a1 = As[cur][kk][tym * 2 + 1];
                    float4 b4 = *reinterpret_cast<const float4*>(&Bs[cur][kk][txn * 4]);
                    acc[0][0] += a0 * b4.x; acc[0][1] += a0 * b4.y;
                    acc[0][2] += a0 * b4.z; acc[0][3] += a0 * b4.w;
                    acc[1][0] += a1 * b4.x; acc[1][1] += a1 * b4.y;
                    acc[1][2] += a1 * b4.z; acc[1][3] += a1 * b4.w;
                }
                cur ^= 1;
            }
            __syncthreads();
#pragma unroll
            for (int i = 0; i < 2; ++i) {
                int m = m0 + tym * 2 + i;
#pragma unroll
                for (int c = 0; c < 4; ++c) {
                    int nc = n0 + txn * 4 + c;
                    if (nc < 3 * VOC)
                        rec[(size_t)m * (3 * VOC) + nc] = acc[i][c] + ba1[nc];
                }
            }
        }
        grid_barrier(G, sense);

        // ----- phase B: gates + softmax + combine -----
        if (blockIdx.x < BATCH) {
            const int b = blockIdx.x;
            const float* xrow = xza + ((size_t)b * NSENT + n) * (3 * VOC);
            const float* rrow = rec + (size_t)b * (3 * VOC);
            float zv[8], tv[8];
            float m = -1e30f;
#pragma unroll
            for (int i = 0; i < 8; ++i) {
                int jj = tid + i * 256;
                if (jj < VOC) {
                    float z = sigmoidf_(xrow[jj] + rrow[jj]);
                    float r = sigmoidf_(xrow[VOC + jj] + rrow[VOC + jj]);
                    float t = xrow[2 * VOC + jj] + r * rrow[2 * VOC + jj];
                    zv[i] = z; tv[i] = t;
                    m = fmaxf(m, t);
                } else { zv[i] = 0.f; tv[i] = -1e30f; }
            }
            red[tid] = m; __syncthreads();
            for (int s = 128; s > 0; s >>= 1) {
                if (tid < s) red[tid] = fmaxf(red[tid], red[tid + s]);
                __syncthreads();
            }
            m = red[0]; __syncthreads();

            float ev[8];
            float sum = 0.f;
#pragma unroll
            for (int i = 0; i < 8; ++i) {
                int jj = tid + i * 256;
                if (jj < VOC) { ev[i] = expf(tv[i] - m); sum += ev[i]; }
                else ev[i] = 0.f;
            }
            red[tid] = sum; __syncthreads();
            for (int s = 128; s > 0; s >>= 1) {
                if (tid < s) red[tid] += red[tid + s];
                __syncthreads();
            }
            const float inv = 1.f / red[0];
            __syncthreads();

#pragma unroll
            for (int i = 0; i < 8; ++i) {
                int jj = tid + i * 256;
                if (jj < VOC) {
                    float hh = ev[i] * inv;
                    float z  = zv[i];
                    float hprev = hp[(size_t)b * VOC + jj];
                    float hnew = z * hprev + (1.f - z) * hh;
                    hn[(size_t)b * VOC + jj] = hnew;
                    out[((size_t)b * NSENT + n) * VOC + jj] = hnew;
                }
            }
        }
        grid_barrier(G, sense);
        float* tmp = hp; hp = hn; hn = tmp;
    }
}

// ---------------------------------------------------------------------------
// Host orchestration
// ---------------------------------------------------------------------------
extern "C" void kernel_launch(void* const* d_in, const int* in_sizes, int n_in,
                              void* d_out, int out_size) {
    const int*   info      = (const int*)d_in[0];
    const int*   info_idx  = (const int*)d_in[1];
    const int*   num_sent  = (const int*)d_in[2];
    const int*   question  = (const int*)d_in[3];
    const int*   qidx      = (const int*)d_in[4];
    const float* info_emb  = (const float*)d_in[5];
    const float* Wi        = (const float*)d_in[6];
    const float* Ui        = (const float*)d_in[7];
    const float* bi        = (const float*)d_in[8];
    const float* q_emb     = (const float*)d_in[9];
    const float* Wq        = (const float*)d_in[10];
    const float* Uq        = (const float*)d_in[11];
    const float* bq        = (const float*)d_in[12];
    const float* Wm        = (const float*)d_in[13];
    const float* Um        = (const float*)d_in[14];
    const float* bm        = (const float*)d_in[15];
    const float* Wa        = (const float*)d_in[16];
    const float* Ua        = (const float*)d_in[17];
    const float* ba        = (const float*)d_in[18];
    float* out = (float*)d_out;

    float *tbl_i, *tbl_q, *hinfo, *hq, *prod, *xzm, *hidden, *xza, *rec, *hA, *hB;
    cudaGetSymbolAddress((void**)&tbl_i, g_table_i);
    cudaGetSymbolAddress((void**)&tbl_q, g_table_q);
    cudaGetSymbolAddress((void**)&hinfo, g_hinfo);
    cudaGetSymbolAddress((void**)&hq, g_hq);
    cudaGetSymbolAddress((void**)&prod, g_prod);
    cudaGetSymbolAddress((void**)&xzm, g_xzm);
    cudaGetSymbolAddress((void**)&hidden, g_hidden);
    cudaGetSymbolAddress((void**)&xza, g_xza);
    cudaGetSymbolAddress((void**)&rec, g_rec);
    cudaGetSymbolAddress((void**)&hA, g_hA);
    cudaGetSymbolAddress((void**)&hB, g_hB);

    static bool attr_set = false;
    if (!attr_set) {
        cudaFuncSetAttribute(gru_seq_kernel,
                             cudaFuncAttributeMaxDynamicSharedMemorySize, 200 * 1024);
        attr_set = true;
    }

    build_table_kernel<<<dim3((3 * RUN + 255) / 256, 1024), 256>>>(info_emb, Wi, bi, tbl_i, 3 * RUN);
    build_table_kernel<<<dim3((3 * RUN + 255) / 256, 64), 256>>>(q_emb, Wq, bq, tbl_q, 3 * RUN);

    const dim3 blk(32, 4);

    // info GRU (T=1024, H=400): 13x8 = 104 CTAs
    {
        size_t smem = (size_t)RUN * 96 * 4 + (size_t)16 * RUN * 4;
        gru_seq_kernel<<<dim3((RUN + 31) / 32, 8), blk, smem>>>(
            tbl_i, info, Ui, bi + 3 * RUN, hA, hB, hinfo, nullptr, SLEN, RUN);
    }
    // question GRU (T=64, H=400)
    {
        size_t smem = (size_t)RUN * 96 * 4 + (size_t)16 * RUN * 4;
        gru_seq_kernel<<<dim3((RUN + 31) / 32, 8), blk, smem>>>(
            tbl_q, question, Uq, bq + 3 * RUN, hA, hB, hq, nullptr, QLEN, RUN);
    }

    prod_kernel<<<dim3(NSENT, BATCH), 128>>>(hinfo, hq, info_idx, num_sent, qidx, prod);

    gemm_bias_kernel<<<dim3((3 * MEM + 63) / 64, (BATCH * NSENT) / 64), 256>>>(
        prod, Wm, bm, xzm, BATCH * NSENT, RUN, 3 * MEM);

    // memory GRU (T=64, H=300): 10x8 = 80 CTAs
    {
        size_t smem = (size_t)MEM * 96 * 4 + (size_t)16 * MEM * 4;
        gru_seq_kernel<<<dim3((MEM + 31) / 32, 8), blk, smem>>>(
            xzm, nullptr, Um, bm + 3 * MEM, hA, hB, hidden, num_sent, NSENT, MEM);
    }

    gemm_bias_kernel<<<dim3((3 * VOC + 63) / 64, (BATCH * NSENT) / 64), 256>>>(
        hidden, Wa, ba, xza, BATCH * NSENT, MEM, 3 * VOC);

    answer_kernel<<<ANS_G, 256>>>(xza, Ua, ba + 3 * VOC, rec, hA, hB, out);
}